// round 12
// baseline (speedup 1.0000x reference)
#include <cuda_runtime.h>
#include <cuda_fp16.h>
#include <cstdint>

// out[b,o,d0,d1,p2,p3] = bias[o] + sum_{chunk,l,k1,k2,k3} w[chunk,o,l,k1,k2,k3] *
//   xp[b, cin, e0, d1+k1-1, p2+k2-1, p3+k3-1],  Labs=(d0+chunk)*32+l, cin=Labs/26, e0=Labs%26-1
// Implicit GEMM via mma.sync m16n8k16 fp16 (fp32 accum).
// CTA = (b,d0,d1) x (M-half) x (N-half): D[320 anchors][32 oc]. 2 CTAs/SM for latency coverage.

#define DDIM 24
#define AR 374                   // A rows per slot (320 anchors + 54 shift margin)
#define ASL 5984                 // u32 per A slot (AR * 16)
#define BSL 4608                 // u32 per B slot (9 taps * 32 oc * 16)
#define X2N 26996736             // halves: 2*24*676*832

__device__ __align__(16) __half W2h[165888];  // [pr][oc 64][l 32] fp16
__device__ __align__(16) __half X2h[X2N];     // [b][e1][q 676][Labs 832] fp16, borders zero

__device__ __forceinline__ void cpasync8(const uint32_t* smem_dst, const __half* gsrc) {
    unsigned a = (unsigned)__cvta_generic_to_shared(smem_dst);
    asm volatile("cp.async.ca.shared.global [%0], [%1], 8;" :: "r"(a), "l"(gsrc) : "memory");
}
__device__ __forceinline__ void mma16(float& c0, float& c1, float& c2, float& c3,
                                      uint32_t a0, uint32_t a1, uint32_t a2, uint32_t a3,
                                      uint32_t b0, uint32_t b1) {
    asm volatile("mma.sync.aligned.m16n8k16.row.col.f32.f16.f16.f32 "
                 "{%0,%1,%2,%3},{%4,%5,%6,%7},{%8,%9},{%0,%1,%2,%3};"
                 : "+f"(c0), "+f"(c1), "+f"(c2), "+f"(c3)
                 : "r"(a0), "r"(a1), "r"(a2), "r"(a3), "r"(b0), "r"(b1));
}

// ---------------- prepass: weights ----------------
__global__ void wprep_kernel(const float* __restrict__ w) {
    int idx = blockIdx.x * 256 + threadIdx.x;
    if (idx < 165888) {
        int l = idx & 31;
        int r = idx >> 5;
        int oc = r & 63; r >>= 6;
        int t = r % 9;  r /= 9;
        int k1 = r % 3;
        int chunk = r / 3;
        W2h[idx] = __float2half_rn(w[((chunk * 64 + oc) * 32 + l) * 27 + k1 * 9 + t]);
    }
}

// ---------------- prepass: zero X2h ----------------
__global__ void xzero_kernel() {
    size_t i = (size_t)blockIdx.x * 1024 + threadIdx.x;
    if (i < X2N / 8) {
        uint4 z = make_uint4(0, 0, 0, 0);
        ((uint4*)X2h)[i] = z;
    }
}

// ---------------- prepass: interior transpose x -> X2h ----------------
__global__ void xprep_kernel(const float* __restrict__ x) {
    extern __shared__ float sp[];
    const int bid = blockIdx.x;
    const int e1  = bid % 24;
    const int cin = (bid / 24) % 32;
    const int b   = bid / 768;
    const int tid = threadIdx.x;

    const float* base = x + (size_t)(b * 32 + cin) * 331776 + e1 * 576;
    for (int i = tid; i < 13824; i += 256) {
        const int e0  = i / 576;
        const int rem = i - e0 * 576;
        sp[e0 * 577 + rem] = __ldg(base + e0 * 13824 + rem);
    }
    __syncthreads();
    const size_t dbase = (size_t)(b * 24 + e1) * 562432 + cin * 26;
    for (int j = tid; j < 13824; j += 256) {
        const int y    = j / 576;
        const int rem2 = j - y * 576;
        const int z    = rem2 / 24;
        const int e0   = rem2 - z * 24;
        X2h[dbase + (size_t)((y + 1) * 26 + (z + 1)) * 832 + (e0 + 1)] =
            __float2half_rn(sp[e0 * 577 + y * 24 + z]);
    }
}

// ---------------- main kernel ----------------
__global__ __launch_bounds__(256, 2)
void conv4d_mma_kernel(const float* __restrict__ bias,
                       float* __restrict__ out)
{
    extern __shared__ float sm[];
    float*    bs  = sm;                       // 32 floats (this CTA's oc range)
    uint32_t* A0u = (uint32_t*)(sm + 32);
    uint32_t* A1u = A0u + ASL;
    uint32_t* B0u = A1u + ASL;
    uint32_t* B1u = B0u + BSL;

    const int blk  = blockIdx.x;              // b*576 + d0*24 + d1
    const int d1   = blk % DDIM;
    const int t0   = blk / DDIM;
    const int d0   = t0 % DDIM;
    const int b    = t0 / DDIM;
    const int half = blockIdx.y;
    const int qoff = half * 320;
    const int oc0  = blockIdx.z * 32;         // N half

    const int tid   = threadIdx.x;
    const int wid   = tid >> 5;
    const int lane  = tid & 31;
    const int wm    = wid & 3;                // M slab: local anchors [wm*80, +80)
    const int wn    = wid >> 2;               // N quarter: oc0 + [wn*16, +16)
    const int laneq = lane >> 2;
    const int lanec = lane & 3;

    if (tid < 32) bs[tid] = bias[oc0 + tid];

    // zero junk rows (qglobal >= 676) of both A slots, once
    {
        const int jstart = 676 - qoff;        // 676 (none) or 356
        if (jstart < AR) {
            for (int i = jstart * 16 + tid; i < AR * 16; i += 256) {
                A0u[i] = 0u;
                A1u[i] = 0u;
            }
        }
    }

    // valid (chunk,k1) pairs
    int prs[9]; int np = 0;
    #pragma unroll
    for (int chunk = 0; chunk < 3; chunk++)
        #pragma unroll
        for (int k1 = 0; k1 < 3; k1++) {
            const int e1 = d1 + k1 - 1;
            if ((unsigned)e1 < (unsigned)DDIM) prs[np++] = chunk * 3 + k1;
        }

    float cc[5][2][4];
    #pragma unroll
    for (int i = 0; i < 5; i++)
        #pragma unroll
        for (int j = 0; j < 2; j++)
            #pragma unroll
            for (int k = 0; k < 4; k++) cc[i][j][k] = 0.0f;

    auto stageA = [&](int pr, uint32_t* Ad) {
        const int chunk = pr / 3, k1 = pr - 3 * chunk;
        const int e1 = d1 + k1 - 1;
        const __half* src = X2h + (size_t)(b * 24 + e1) * 562432 + (d0 + chunk) * 32;
        #pragma unroll
        for (int k = 0; k < 12; k++) {
            const int gid = tid + k * 256;
            if (gid < AR * 8) {
                const int r = gid >> 3, g = gid & 7;
                const int qg = qoff + r;
                if (qg < 676)
                    cpasync8(Ad + r * 16 + ((g * 2) ^ ((r & 7) << 1)),
                             src + (size_t)qg * 832 + g * 4);
            }
        }
    };
    auto stageB = [&](int pr, uint32_t* Bd) {
        const __half* wsrc = W2h + pr * 18432 + oc0 * 32;
        #pragma unroll
        for (int i = 0; i < 9; i++) {
            const int gid = tid + i * 256;    // < 2304
            const int tap = gid >> 8, rem = gid & 255;
            const int oc  = rem >> 3, g = rem & 7;
            cpasync8(Bd + tap * 512 + oc * 16 + ((g * 2) ^ ((oc & 7) << 1)),
                     wsrc + tap * 2048 + oc * 32 + g * 4);
        }
    };

    // prologue: stage iter 0
    stageA(prs[0], A0u);
    stageB(prs[0], B0u);
    asm volatile("cp.async.commit_group;" ::: "memory");
    asm volatile("cp.async.wait_group 0;" ::: "memory");
    __syncthreads();

    for (int it = 0; it < np; it++) {
        const bool more = (it + 1 < np);
        if (more) {                            // hidden behind compute
            stageA(prs[it + 1], (it & 1) ? A0u : A1u);
            stageB(prs[it + 1], (it & 1) ? B0u : B1u);
            asm volatile("cp.async.commit_group;" ::: "memory");
        }

        const uint32_t* Au = (it & 1) ? A1u : A0u;
        const uint32_t* Bu = (it & 1) ? B1u : B0u;

        for (int tap = 0; tap < 9; tap++) {
            const int shift = (tap / 3) * 26 + (tap % 3);
            const int rbase = wm * 80 + shift + laneq;
            const int xr    = (rbase & 7) << 1;
            const int arow  = rbase * 16;
            const int tapo  = tap * 512;
            const int xb    = laneq << 1;
            #pragma unroll
            for (int ks = 0; ks < 2; ks++) {
                const int c0 = ks * 8 + lanec;
                uint32_t fb0[2], fb1[2];
                #pragma unroll
                for (int n8 = 0; n8 < 2; n8++) {
                    const int ob = tapo + (wn * 16 + n8 * 8 + laneq) * 16;
                    fb0[n8] = Bu[ob + (c0 ^ xb)];
                    fb1[n8] = Bu[ob + ((c0 + 4) ^ xb)];
                }
                const int ca0 = c0 ^ xr, ca2 = (c0 + 4) ^ xr;
                #pragma unroll
                for (int t16 = 0; t16 < 5; t16++) {
                    const int ab = arow + t16 * 256;
                    const uint32_t a0 = Au[ab + ca0];
                    const uint32_t a1 = Au[ab + 128 + ca0];
                    const uint32_t a2 = Au[ab + ca2];
                    const uint32_t a3 = Au[ab + 128 + ca2];
                    #pragma unroll
                    for (int n8 = 0; n8 < 2; n8++)
                        mma16(cc[t16][n8][0], cc[t16][n8][1], cc[t16][n8][2], cc[t16][n8][3],
                              a0, a1, a2, a3, fb0[n8], fb1[n8]);
                }
            }
        }

        if (more) asm volatile("cp.async.wait_group 0;" ::: "memory");
        __syncthreads();
    }

    // epilogue: bias + store valid anchors
    const size_t ob = (size_t)b * 21233664 + (size_t)d0 * 13824 + (size_t)d1 * 576;
    #pragma unroll
    for (int t16 = 0; t16 < 5; t16++) {
        const int qa = qoff + wm * 80 + t16 * 16 + laneq;
        const int qb = qa + 8;
        const int p2a = qa / 26, p3a = qa - p2a * 26;
        const int p2b = qb / 26, p3b = qb - p2b * 26;
        const bool va = (p2a < DDIM) && (p3a < DDIM);
        const bool vb = (p2b < DDIM) && (p3b < DDIM);
        #pragma unroll
        for (int n8 = 0; n8 < 2; n8++) {
            const int ocl = wn * 16 + n8 * 8 + lanec * 2;
            const float bv0 = bs[ocl], bv1 = bs[ocl + 1];
            float* o0 = out + ob + (size_t)(oc0 + ocl) * 331776;
            if (va) {
                o0[p2a * 24 + p3a]          = cc[t16][n8][0] + bv0;
                o0[331776 + p2a * 24 + p3a] = cc[t16][n8][1] + bv1;
            }
            if (vb) {
                o0[p2b * 24 + p3b]          = cc[t16][n8][2] + bv0;
                o0[331776 + p2b * 24 + p3b] = cc[t16][n8][3] + bv1;
            }
        }
    }
}

extern "C" void kernel_launch(void* const* d_in, const int* in_sizes, int n_in,
                              void* d_out, int out_size)
{
    const float* x = nullptr;
    const float* w = nullptr;
    const float* bias = nullptr;
    for (int k = 0; k < n_in; k++) {
        if (in_sizes[k] == 2 * 32 * 24 * 24 * 24 * 24) x    = (const float*)d_in[k];
        else if (in_sizes[k] == 3 * 64 * 32 * 27)      w    = (const float*)d_in[k];
        else if (in_sizes[k] == 64)                    bias = (const float*)d_in[k];
    }
    float* out = (float*)d_out;

    wprep_kernel<<<(165888 + 255) / 256, 256>>>(w);
    xzero_kernel<<<(X2N / 8 + 1023) / 1024, 1024>>>();
    const int xp_smem = 24 * 577 * 4;   // 55392
    cudaFuncSetAttribute(xprep_kernel, cudaFuncAttributeMaxDynamicSharedMemorySize, xp_smem);
    xprep_kernel<<<2 * 32 * 24, 256, xp_smem>>>(x);

    const int smem_bytes = 32 * 4 + (2 * ASL + 2 * BSL) * 4;   // 84864
    cudaFuncSetAttribute(conv4d_mma_kernel, cudaFuncAttributeMaxDynamicSharedMemorySize, smem_bytes);
    dim3 grid(2 * 24 * 24, 2, 2);
    conv4d_mma_kernel<<<grid, 256, smem_bytes>>>(bias, out);
}

// round 13
// speedup vs baseline: 1.1673x; 1.1673x over previous
#include <cuda_runtime.h>
#include <cuda_fp16.h>
#include <cstdint>

// out[b,o,d0,d1,p2,p3] = bias[o] + sum_{chunk,l,k1,k2,k3} w[chunk,o,l,k1,k2,k3] *
//   xp[b, cin, e0, d1+k1-1, p2+k2-1, p3+k3-1],  Labs=(d0+chunk)*32+l, cin=Labs/26, e0=Labs%26-1
// Implicit GEMM via mma.sync m16n8k16 fp16 (fp32 accum).
// CTA = (b,d0,d1): D[640 anchors][64 oc], 512 threads (16 warps = 8 M-slabs x 2 N-halves).

#define DDIM 24
#define AR 704                   // A rows per slot (622 valid anchors + 54 shift + margin)
#define ASL 11264                // u32 per A slot (AR * 16)
#define BSL 9216                 // u32 per B slot (9 taps * 64 oc * 16)
#define X2N 26996736             // halves: 2*24*676*832

__device__ __align__(16) __half W2h[165888];  // [pr][oc 64][l 32] fp16
__device__ __align__(16) __half X2h[X2N];     // [b][e1][q 676][Labs 832] fp16, borders zero

__device__ __forceinline__ void cpasync8(const uint32_t* smem_dst, const __half* gsrc) {
    unsigned a = (unsigned)__cvta_generic_to_shared(smem_dst);
    asm volatile("cp.async.ca.shared.global [%0], [%1], 8;" :: "r"(a), "l"(gsrc) : "memory");
}
__device__ __forceinline__ void mma16(float& c0, float& c1, float& c2, float& c3,
                                      uint32_t a0, uint32_t a1, uint32_t a2, uint32_t a3,
                                      uint32_t b0, uint32_t b1) {
    asm volatile("mma.sync.aligned.m16n8k16.row.col.f32.f16.f16.f32 "
                 "{%0,%1,%2,%3},{%4,%5,%6,%7},{%8,%9},{%0,%1,%2,%3};"
                 : "+f"(c0), "+f"(c1), "+f"(c2), "+f"(c3)
                 : "r"(a0), "r"(a1), "r"(a2), "r"(a3), "r"(b0), "r"(b1));
}

// ---------------- prepass: weights ----------------
__global__ void wprep_kernel(const float* __restrict__ w) {
    int idx = blockIdx.x * 256 + threadIdx.x;
    if (idx < 165888) {
        int l = idx & 31;
        int r = idx >> 5;
        int oc = r & 63; r >>= 6;
        int t = r % 9;  r /= 9;
        int k1 = r % 3;
        int chunk = r / 3;
        W2h[idx] = __float2half_rn(w[((chunk * 64 + oc) * 32 + l) * 27 + k1 * 9 + t]);
    }
}

// ---------------- prepass: zero X2h ----------------
__global__ void xzero_kernel() {
    size_t i = (size_t)blockIdx.x * 1024 + threadIdx.x;
    if (i < X2N / 8) {
        uint4 z = make_uint4(0, 0, 0, 0);
        ((uint4*)X2h)[i] = z;
    }
}

// ---------------- prepass: interior transpose x -> X2h ----------------
__global__ void xprep_kernel(const float* __restrict__ x) {
    extern __shared__ float sp[];
    const int bid = blockIdx.x;
    const int e1  = bid % 24;
    const int cin = (bid / 24) % 32;
    const int b   = bid / 768;
    const int tid = threadIdx.x;

    const float* base = x + (size_t)(b * 32 + cin) * 331776 + e1 * 576;
    for (int i = tid; i < 13824; i += 256) {
        const int e0  = i / 576;
        const int rem = i - e0 * 576;
        sp[e0 * 577 + rem] = __ldg(base + e0 * 13824 + rem);
    }
    __syncthreads();
    const size_t dbase = (size_t)(b * 24 + e1) * 562432 + cin * 26;
    for (int j = tid; j < 13824; j += 256) {
        const int y    = j / 576;
        const int rem2 = j - y * 576;
        const int z    = rem2 / 24;
        const int e0   = rem2 - z * 24;
        X2h[dbase + (size_t)((y + 1) * 26 + (z + 1)) * 832 + (e0 + 1)] =
            __float2half_rn(sp[e0 * 577 + y * 24 + z]);
    }
}

// ---------------- main kernel ----------------
__global__ __launch_bounds__(512, 1)
void conv4d_mma_kernel(const float* __restrict__ bias,
                       float* __restrict__ out)
{
    extern __shared__ float sm[];
    float*    bs  = sm;                       // 64 floats
    uint32_t* A0u = (uint32_t*)(sm + 64);
    uint32_t* A1u = A0u + ASL;
    uint32_t* B0u = A1u + ASL;
    uint32_t* B1u = B0u + BSL;

    const int blk  = blockIdx.x;              // b*576 + d0*24 + d1
    const int d1   = blk % DDIM;
    const int t0   = blk / DDIM;
    const int d0   = t0 % DDIM;
    const int b    = t0 / DDIM;

    const int tid   = threadIdx.x;
    const int wid   = tid >> 5;
    const int lane  = tid & 31;
    const int wm    = wid & 7;                // M slab: anchors [wm*80, +80)
    const int wn    = wid >> 3;               // N half: oc [wn*32, +32)
    const int laneq = lane >> 2;
    const int lanec = lane & 3;

    if (tid < 64) bs[tid] = bias[tid];

    // zero junk rows (q >= 676) of both A slots, once (448 u32 per slot)
    if (tid < 448) {
        A0u[676 * 16 + tid] = 0u;
        A1u[676 * 16 + tid] = 0u;
    }

    // valid (chunk,k1) pairs
    int prs[9]; int np = 0;
    #pragma unroll
    for (int chunk = 0; chunk < 3; chunk++)
        #pragma unroll
        for (int k1 = 0; k1 < 3; k1++) {
            const int e1 = d1 + k1 - 1;
            if ((unsigned)e1 < (unsigned)DDIM) prs[np++] = chunk * 3 + k1;
        }

    float cc[5][4][4];
    #pragma unroll
    for (int i = 0; i < 5; i++)
        #pragma unroll
        for (int j = 0; j < 4; j++)
            #pragma unroll
            for (int k = 0; k < 4; k++) cc[i][j][k] = 0.0f;

    auto stageA = [&](int pr, uint32_t* Ad) {
        const int chunk = pr / 3, k1 = pr - 3 * chunk;
        const int e1 = d1 + k1 - 1;
        const __half* src = X2h + (size_t)(b * 24 + e1) * 562432 + (d0 + chunk) * 32;
        #pragma unroll
        for (int k = 0; k < 11; k++) {
            const int gid = tid + k * 512;
            if (gid < 676 * 8) {
                const int r = gid >> 3, g = gid & 7;
                cpasync8(Ad + r * 16 + ((g * 2) ^ ((r & 7) << 1)),
                         src + (size_t)r * 832 + g * 4);
            }
        }
    };
    auto stageB = [&](int pr, uint32_t* Bd) {
        const __half* wsrc = W2h + pr * 18432;
        #pragma unroll
        for (int i = 0; i < 9; i++) {
            const int gid = tid + i * 512;    // < 4608
            const int tap = gid >> 9, rem = gid & 511;
            const int oc  = rem >> 3, g = rem & 7;
            cpasync8(Bd + tap * 1024 + oc * 16 + ((g * 2) ^ ((oc & 7) << 1)),
                     wsrc + tap * 2048 + oc * 32 + g * 4);
        }
    };

    // prologue: stage iter 0
    stageA(prs[0], A0u);
    stageB(prs[0], B0u);
    asm volatile("cp.async.commit_group;" ::: "memory");
    asm volatile("cp.async.wait_group 0;" ::: "memory");
    __syncthreads();

    for (int it = 0; it < np; it++) {
        const bool more = (it + 1 < np);
        if (more) {                            // hidden behind compute
            stageA(prs[it + 1], (it & 1) ? A0u : A1u);
            stageB(prs[it + 1], (it & 1) ? B0u : B1u);
            asm volatile("cp.async.commit_group;" ::: "memory");
        }

        const uint32_t* Au = (it & 1) ? A1u : A0u;
        const uint32_t* Bu = (it & 1) ? B1u : B0u;

        for (int tap = 0; tap < 9; tap++) {
            const int shift = (tap / 3) * 26 + (tap % 3);
            const int rbase = wm * 80 + shift + laneq;
            const int xr    = (rbase & 7) << 1;
            const int arow  = rbase * 16;
            const int tapo  = tap * 1024;
            const int xb    = laneq << 1;
            #pragma unroll
            for (int ks = 0; ks < 2; ks++) {
                const int c0 = ks * 8 + lanec;
                uint32_t fb0[4], fb1[4];
                #pragma unroll
                for (int n8 = 0; n8 < 4; n8++) {
                    const int ob = tapo + (wn * 32 + n8 * 8 + laneq) * 16;
                    fb0[n8] = Bu[ob + (c0 ^ xb)];
                    fb1[n8] = Bu[ob + ((c0 + 4) ^ xb)];
                }
                const int ca0 = c0 ^ xr, ca2 = (c0 + 4) ^ xr;
                #pragma unroll
                for (int t16 = 0; t16 < 5; t16++) {
                    const int ab = arow + t16 * 256;
                    const uint32_t a0 = Au[ab + ca0];
                    const uint32_t a1 = Au[ab + 128 + ca0];
                    const uint32_t a2 = Au[ab + ca2];
                    const uint32_t a3 = Au[ab + 128 + ca2];
                    #pragma unroll
                    for (int n8 = 0; n8 < 4; n8++)
                        mma16(cc[t16][n8][0], cc[t16][n8][1], cc[t16][n8][2], cc[t16][n8][3],
                              a0, a1, a2, a3, fb0[n8], fb1[n8]);
                }
            }
        }

        if (more) asm volatile("cp.async.wait_group 0;" ::: "memory");
        __syncthreads();
    }

    // epilogue: bias + store valid anchors
    const size_t ob = (size_t)b * 21233664 + (size_t)d0 * 13824 + (size_t)d1 * 576;
    #pragma unroll
    for (int t16 = 0; t16 < 5; t16++) {
        const int qa = wm * 80 + t16 * 16 + laneq;
        const int qb = qa + 8;
        const int p2a = qa / 26, p3a = qa - p2a * 26;
        const int p2b = qb / 26, p3b = qb - p2b * 26;
        const bool va = (p2a < DDIM) && (p3a < DDIM);
        const bool vb = (p2b < DDIM) && (p3b < DDIM);
        #pragma unroll
        for (int n8 = 0; n8 < 4; n8++) {
            const int oc = wn * 32 + n8 * 8 + lanec * 2;
            const float bv0 = bs[oc], bv1 = bs[oc + 1];
            float* o0 = out + ob + (size_t)oc * 331776;
            if (va) {
                o0[p2a * 24 + p3a]          = cc[t16][n8][0] + bv0;
                o0[331776 + p2a * 24 + p3a] = cc[t16][n8][1] + bv1;
            }
            if (vb) {
                o0[p2b * 24 + p3b]          = cc[t16][n8][2] + bv0;
                o0[331776 + p2b * 24 + p3b] = cc[t16][n8][3] + bv1;
            }
        }
    }
}

extern "C" void kernel_launch(void* const* d_in, const int* in_sizes, int n_in,
                              void* d_out, int out_size)
{
    const float* x = nullptr;
    const float* w = nullptr;
    const float* bias = nullptr;
    for (int k = 0; k < n_in; k++) {
        if (in_sizes[k] == 2 * 32 * 24 * 24 * 24 * 24) x    = (const float*)d_in[k];
        else if (in_sizes[k] == 3 * 64 * 32 * 27)      w    = (const float*)d_in[k];
        else if (in_sizes[k] == 64)                    bias = (const float*)d_in[k];
    }
    float* out = (float*)d_out;

    wprep_kernel<<<(165888 + 255) / 256, 256>>>(w);
    xzero_kernel<<<(X2N / 8 + 1023) / 1024, 1024>>>();
    const int xp_smem = 24 * 577 * 4;   // 55392
    cudaFuncSetAttribute(xprep_kernel, cudaFuncAttributeMaxDynamicSharedMemorySize, xp_smem);
    xprep_kernel<<<2 * 32 * 24, 256, xp_smem>>>(x);

    const int smem_bytes = 64 * 4 + (2 * ASL + 2 * BSL) * 4;   // 164096
    cudaFuncSetAttribute(conv4d_mma_kernel, cudaFuncAttributeMaxDynamicSharedMemorySize, smem_bytes);
    conv4d_mma_kernel<<<2 * 24 * 24, 512, smem_bytes>>>(bias, out);
}

// round 15
// speedup vs baseline: 1.2493x; 1.0702x over previous
#include <cuda_runtime.h>
#include <cuda_fp16.h>
#include <cstdint>

// out[b,o,d0,d1,p2,p3] = bias[o] + sum_{chunk,l,k1,k2,k3} w[chunk,o,l,k1,k2,k3] *
//   xp[b, cin, e0, d1+k1-1, p2+k2-1, p3+k3-1],  Labs=(d0+chunk)*32+l, cin=Labs/26, e0=Labs%26-1
// Implicit GEMM via mma.sync m16n8k16 fp16 (fp32 accum), fragments via ldmatrix.x4.
// CTA = (b,d0,d1): D[640 anchors][64 oc], 512 threads (16 warps = 8 M-slabs x 2 N-halves).
// Swizzle (64B rows, 4x16B cols): c16' = c16 ^ ((row>>1)&3)  -- 2-bit key, in-row, ldsm-conflict-free.

#define DDIM 24
#define AR 704                   // A rows per slot
#define ASL 11264                // u32 per A slot (AR * 16)
#define BSL 9216                 // u32 per B slot (9 taps * 64 oc * 16)
#define X2N 26996736             // halves: 2*24*676*832

__device__ __align__(16) __half W2h[165888];  // [pr][oc 64][l 32] fp16
__device__ __align__(16) __half X2h[X2N];     // [b][e1][q 676][Labs 832] fp16, borders zero

__device__ __forceinline__ uint32_t smem_u32p(const void* p) {
    return (uint32_t)__cvta_generic_to_shared(p);
}
__device__ __forceinline__ void cpasync8(const uint32_t* smem_dst, const __half* gsrc) {
    unsigned a = (unsigned)__cvta_generic_to_shared(smem_dst);
    asm volatile("cp.async.ca.shared.global [%0], [%1], 8;" :: "r"(a), "l"(gsrc) : "memory");
}
__device__ __forceinline__ void ldsm4(uint32_t& r0, uint32_t& r1, uint32_t& r2, uint32_t& r3,
                                      uint32_t addr) {
    asm volatile("ldmatrix.sync.aligned.m8n8.x4.shared.b16 {%0,%1,%2,%3}, [%4];"
                 : "=r"(r0), "=r"(r1), "=r"(r2), "=r"(r3) : "r"(addr));
}
__device__ __forceinline__ void mma16(float& c0, float& c1, float& c2, float& c3,
                                      uint32_t a0, uint32_t a1, uint32_t a2, uint32_t a3,
                                      uint32_t b0, uint32_t b1) {
    asm volatile("mma.sync.aligned.m16n8k16.row.col.f32.f16.f16.f32 "
                 "{%0,%1,%2,%3},{%4,%5,%6,%7},{%8,%9},{%0,%1,%2,%3};"
                 : "+f"(c0), "+f"(c1), "+f"(c2), "+f"(c3)
                 : "r"(a0), "r"(a1), "r"(a2), "r"(a3), "r"(b0), "r"(b1));
}

// ---------------- prepass: weights ----------------
__global__ void wprep_kernel(const float* __restrict__ w) {
    int idx = blockIdx.x * 256 + threadIdx.x;
    if (idx < 165888) {
        int l = idx & 31;
        int r = idx >> 5;
        int oc = r & 63; r >>= 6;
        int t = r % 9;  r /= 9;
        int k1 = r % 3;
        int chunk = r / 3;
        W2h[idx] = __float2half_rn(w[((chunk * 64 + oc) * 32 + l) * 27 + k1 * 9 + t]);
    }
}

// ---------------- prepass: zero X2h ----------------
__global__ void xzero_kernel() {
    size_t i = (size_t)blockIdx.x * 1024 + threadIdx.x;
    if (i < X2N / 8) {
        uint4 z = make_uint4(0, 0, 0, 0);
        ((uint4*)X2h)[i] = z;
    }
}

// ---------------- prepass: interior transpose x -> X2h ----------------
__global__ void xprep_kernel(const float* __restrict__ x) {
    extern __shared__ float sp[];
    const int bid = blockIdx.x;
    const int e1  = bid % 24;
    const int cin = (bid / 24) % 32;
    const int b   = bid / 768;
    const int tid = threadIdx.x;

    const float* base = x + (size_t)(b * 32 + cin) * 331776 + e1 * 576;
    for (int i = tid; i < 13824; i += 256) {
        const int e0  = i / 576;
        const int rem = i - e0 * 576;
        sp[e0 * 577 + rem] = __ldg(base + e0 * 13824 + rem);
    }
    __syncthreads();
    const size_t dbase = (size_t)(b * 24 + e1) * 562432 + cin * 26;
    for (int j = tid; j < 13824; j += 256) {
        const int y    = j / 576;
        const int rem2 = j - y * 576;
        const int z    = rem2 / 24;
        const int e0   = rem2 - z * 24;
        X2h[dbase + (size_t)((y + 1) * 26 + (z + 1)) * 832 + (e0 + 1)] =
            __float2half_rn(sp[e0 * 577 + y * 24 + z]);
    }
}

// ---------------- main kernel ----------------
__global__ __launch_bounds__(512, 1)
void conv4d_mma_kernel(const float* __restrict__ bias,
                       float* __restrict__ out)
{
    extern __shared__ float sm[];
    float*    bs  = sm;                       // 64 floats
    uint32_t* A0u = (uint32_t*)(sm + 64);
    uint32_t* A1u = A0u + ASL;
    uint32_t* B0u = A1u + ASL;
    uint32_t* B1u = B0u + BSL;

    const int blk  = blockIdx.x;              // b*576 + d0*24 + d1
    const int d1   = blk % DDIM;
    const int t0   = blk / DDIM;
    const int d0   = t0 % DDIM;
    const int b    = t0 / DDIM;

    const int tid   = threadIdx.x;
    const int wid   = tid >> 5;
    const int lane  = tid & 31;
    const int wm    = wid & 7;                // M slab: anchors [wm*80, +80)
    const int wn    = wid >> 3;               // N half: oc [wn*32, +32)
    const int laneq = lane >> 2;
    const int lanec = lane & 3;

    // ldmatrix per-lane constants
    const int grp      = lane >> 3, lrow = lane & 7;
    const int a_rowoff = ((grp & 1) << 3) + lrow;   // m0/m1 -> rows 0-7 / 8-15
    const int a_khalf  = grp >> 1;                  // m2/m3 -> k+8 (second 16B col)
    const int b_rowoff = ((grp >> 1) << 3) + lrow;  // B: m0/m1 = n8 tile 0 kh0/kh1, m2/m3 = tile1
    const int b_khalf  = grp & 1;
    // B swizzle key: row = wn*32 + b_rowoff (wn*32 = 0 mod 8) -> ((row>>1)&3) = (lrow>>1)&3... 
    // careful: b_rowoff includes +8 for grp>=2, (8>>1)&3 = 0 mod 4? (x+8)>>1 = x>>1 + 4 -> &3 same. OK.
    const uint32_t bxor = (uint32_t)(((b_rowoff >> 1) & 3) << 4);

    if (tid < 64) bs[tid] = bias[tid];

    // zero junk rows (q >= 676) of both A slots, once
    if (tid < 448) {
        A0u[676 * 16 + tid] = 0u;
        A1u[676 * 16 + tid] = 0u;
    }

    // valid (chunk,k1) pairs
    int prs[9]; int np = 0;
    #pragma unroll
    for (int chunk = 0; chunk < 3; chunk++)
        #pragma unroll
        for (int k1 = 0; k1 < 3; k1++) {
            const int e1 = d1 + k1 - 1;
            if ((unsigned)e1 < (unsigned)DDIM) prs[np++] = chunk * 3 + k1;
        }

    float cc[5][4][4];
    #pragma unroll
    for (int i = 0; i < 5; i++)
        #pragma unroll
        for (int j = 0; j < 4; j++)
            #pragma unroll
            for (int k = 0; k < 4; k++) cc[i][j][k] = 0.0f;

    // staging: 8B store granule g of row r -> u32 idx = r*16 + ((g>>1)^((r>>1)&3))*4 + (g&1)*2
    auto stageA = [&](int pr, uint32_t* Ad) {
        const int chunk = pr / 3, k1 = pr - 3 * chunk;
        const int e1 = d1 + k1 - 1;
        const __half* src = X2h + (size_t)(b * 24 + e1) * 562432 + (d0 + chunk) * 32;
        #pragma unroll
        for (int k = 0; k < 11; k++) {
            const int gid = tid + k * 512;
            if (gid < 676 * 8) {
                const int r = gid >> 3, g = gid & 7;
                cpasync8(Ad + r * 16 + (((g >> 1) ^ ((r >> 1) & 3)) << 2) + ((g & 1) << 1),
                         src + (size_t)r * 832 + g * 4);
            }
        }
    };
    auto stageB = [&](int pr, uint32_t* Bd) {
        const __half* wsrc = W2h + pr * 18432;
        #pragma unroll
        for (int i = 0; i < 9; i++) {
            const int gid = tid + i * 512;    // < 4608
            const int tap = gid >> 9, rem = gid & 511;
            const int oc  = rem >> 3, g = rem & 7;
            cpasync8(Bd + tap * 1024 + oc * 16 + (((g >> 1) ^ ((oc >> 1) & 3)) << 2) + ((g & 1) << 1),
                     wsrc + tap * 2048 + oc * 32 + g * 4);
        }
    };

    // prologue: stage iter 0
    stageA(prs[0], A0u);
    stageB(prs[0], B0u);
    asm volatile("cp.async.commit_group;" ::: "memory");
    asm volatile("cp.async.wait_group 0;" ::: "memory");
    __syncthreads();

    const uint32_t aB0 = smem_u32p(A0u), aB1 = smem_u32p(A1u);
    const uint32_t bB0 = smem_u32p(B0u), bB1 = smem_u32p(B1u);
    const uint32_t bRow = (uint32_t)(wn * 32 + b_rowoff) * 64;

    for (int it = 0; it < np; it++) {
        const bool more = (it + 1 < np);
        if (more) {                            // hidden behind compute
            stageA(prs[it + 1], (it & 1) ? A0u : A1u);
            stageB(prs[it + 1], (it & 1) ? B0u : B1u);
            asm volatile("cp.async.commit_group;" ::: "memory");
        }

        const uint32_t aB = (it & 1) ? aB1 : aB0;
        const uint32_t bB = ((it & 1) ? bB1 : bB0) + bRow;

        for (int tap = 0; tap < 9; tap++) {
            const int shift = (tap / 3) * 26 + (tap % 3);
            const int arow  = wm * 80 + shift + a_rowoff;
            const uint32_t axor  = (uint32_t)(((arow >> 1) & 3) << 4);  // stable over t16 (+16 rows)
            const uint32_t abase = aB + (uint32_t)arow * 64;
            const uint32_t btap  = bB + (uint32_t)tap * 4096;
            #pragma unroll
            for (int ks = 0; ks < 2; ks++) {
                const uint32_t akc = ((uint32_t)((ks * 2 + a_khalf) << 4)) ^ axor;
                const uint32_t bkc = ((uint32_t)((ks * 2 + b_khalf) << 4)) ^ bxor;
                uint32_t fb[8];
                ldsm4(fb[0], fb[1], fb[2], fb[3], btap + bkc);           // n8 tiles 0,1
                ldsm4(fb[4], fb[5], fb[6], fb[7], btap + 1024 + bkc);    // n8 tiles 2,3
                #pragma unroll
                for (int t16 = 0; t16 < 5; t16++) {
                    uint32_t a0, a1, a2, a3;
                    ldsm4(a0, a1, a2, a3, abase + (uint32_t)t16 * 1024 + akc);
                    mma16(cc[t16][0][0], cc[t16][0][1], cc[t16][0][2], cc[t16][0][3],
                          a0, a1, a2, a3, fb[0], fb[1]);
                    mma16(cc[t16][1][0], cc[t16][1][1], cc[t16][1][2], cc[t16][1][3],
                          a0, a1, a2, a3, fb[2], fb[3]);
                    mma16(cc[t16][2][0], cc[t16][2][1], cc[t16][2][2], cc[t16][2][3],
                          a0, a1, a2, a3, fb[4], fb[5]);
                    mma16(cc[t16][3][0], cc[t16][3][1], cc[t16][3][2], cc[t16][3][3],
                          a0, a1, a2, a3, fb[6], fb[7]);
                }
            }
        }

        if (more) asm volatile("cp.async.wait_group 0;" ::: "memory");
        __syncthreads();
    }

    // epilogue: bias + store valid anchors
    const size_t ob = (size_t)b * 21233664 + (size_t)d0 * 13824 + (size_t)d1 * 576;
    #pragma unroll
    for (int t16 = 0; t16 < 5; t16++) {
        const int qa = wm * 80 + t16 * 16 + laneq;
        const int qb = qa + 8;
        const int p2a = qa / 26, p3a = qa - p2a * 26;
        const int p2b = qb / 26, p3b = qb - p2b * 26;
        const bool va = (p2a < DDIM) && (p3a < DDIM);
        const bool vb = (p2b < DDIM) && (p3b < DDIM);
        #pragma unroll
        for (int n8 = 0; n8 < 4; n8++) {
            const int oc = wn * 32 + n8 * 8 + lanec * 2;
            const float bv0 = bs[oc], bv1 = bs[oc + 1];
            float* o0 = out + ob + (size_t)oc * 331776;
            if (va) {
                o0[p2a * 24 + p3a]          = cc[t16][n8][0] + bv0;
                o0[331776 + p2a * 24 + p3a] = cc[t16][n8][1] + bv1;
            }
            if (vb) {
                o0[p2b * 24 + p3b]          = cc[t16][n8][2] + bv0;
                o0[331776 + p2b * 24 + p3b] = cc[t16][n8][3] + bv1;
            }
        }
    }
}

extern "C" void kernel_launch(void* const* d_in, const int* in_sizes, int n_in,
                              void* d_out, int out_size)
{
    const float* x = nullptr;
    const float* w = nullptr;
    const float* bias = nullptr;
    for (int k = 0; k < n_in; k++) {
        if (in_sizes[k] == 2 * 32 * 24 * 24 * 24 * 24) x    = (const float*)d_in[k];
        else if (in_sizes[k] == 3 * 64 * 32 * 27)      w    = (const float*)d_in[k];
        else if (in_sizes[k] == 64)                    bias = (const float*)d_in[k];
    }
    float* out = (float*)d_out;

    wprep_kernel<<<(165888 + 255) / 256, 256>>>(w);
    xzero_kernel<<<(X2N / 8 + 1023) / 1024, 1024>>>();
    const int xp_smem = 24 * 577 * 4;   // 55392
    cudaFuncSetAttribute(xprep_kernel, cudaFuncAttributeMaxDynamicSharedMemorySize, xp_smem);
    xprep_kernel<<<2 * 32 * 24, 256, xp_smem>>>(x);

    const int smem_bytes = 64 * 4 + (2 * ASL + 2 * BSL) * 4;   // 164096
    cudaFuncSetAttribute(conv4d_mma_kernel, cudaFuncAttributeMaxDynamicSharedMemorySize, smem_bytes);
    conv4d_mma_kernel<<<2 * 24 * 24, 512, smem_bytes>>>(bias, out);
}

// round 16
// speedup vs baseline: 1.3001x; 1.0407x over previous
#include <cuda_runtime.h>
#include <cuda_fp16.h>
#include <cstdint>

// out[b,o,d0,d1,p2,p3] = bias[o] + sum_{chunk,l,k1,k2,k3} w[chunk,o,l,k1,k2,k3] *
//   xp[b, cin, e0, d1+k1-1, p2+k2-1, p3+k3-1],  Labs=(d0+chunk)*32+l, cin=Labs/26, e0=Labs%26-1
// Implicit GEMM via mma.sync m16n8k16 fp16 (fp32 accum), ldmatrix fragments,
// explicit register double-buffering of fragments (software pipeline).
// CTA = (b,d0,d1): D[640 anchors][64 oc], 512 threads (16 warps = 8 M-slabs x 2 N-halves).
// Swizzle (64B rows, 4x16B cols): c16' = c16 ^ ((row>>1)&3).

#define DDIM 24
#define AR 704
#define ASL 11264                // u32 per A slot (AR * 16)
#define BSL 9216                 // u32 per B slot (9 taps * 64 oc * 16)
#define X2N 26996736             // halves: 2*24*676*832

__device__ __align__(16) __half W2h[165888];  // [pr][oc 64][l 32] fp16
__device__ __align__(16) __half X2h[X2N];     // [b][e1][q 676][Labs 832] fp16, borders zero

__device__ __forceinline__ uint32_t smem_u32p(const void* p) {
    return (uint32_t)__cvta_generic_to_shared(p);
}
__device__ __forceinline__ void cpasync8(const uint32_t* smem_dst, const __half* gsrc) {
    unsigned a = (unsigned)__cvta_generic_to_shared(smem_dst);
    asm volatile("cp.async.ca.shared.global [%0], [%1], 8;" :: "r"(a), "l"(gsrc) : "memory");
}
__device__ __forceinline__ void ldsm4(uint32_t* r, uint32_t addr) {
    asm volatile("ldmatrix.sync.aligned.m8n8.x4.shared.b16 {%0,%1,%2,%3}, [%4];"
                 : "=r"(r[0]), "=r"(r[1]), "=r"(r[2]), "=r"(r[3]) : "r"(addr));
}
__device__ __forceinline__ void mma16(float& c0, float& c1, float& c2, float& c3,
                                      const uint32_t* a, uint32_t b0, uint32_t b1) {
    asm volatile("mma.sync.aligned.m16n8k16.row.col.f32.f16.f16.f32 "
                 "{%0,%1,%2,%3},{%4,%5,%6,%7},{%8,%9},{%0,%1,%2,%3};"
                 : "+f"(c0), "+f"(c1), "+f"(c2), "+f"(c3)
                 : "r"(a[0]), "r"(a[1]), "r"(a[2]), "r"(a[3]), "r"(b0), "r"(b1));
}

// ---------------- prepass: weights ----------------
__global__ void wprep_kernel(const float* __restrict__ w) {
    int idx = blockIdx.x * 256 + threadIdx.x;
    if (idx < 165888) {
        int l = idx & 31;
        int r = idx >> 5;
        int oc = r & 63; r >>= 6;
        int t = r % 9;  r /= 9;
        int k1 = r % 3;
        int chunk = r / 3;
        W2h[idx] = __float2half_rn(w[((chunk * 64 + oc) * 32 + l) * 27 + k1 * 9 + t]);
    }
}

// ---------------- prepass: zero X2h ----------------
__global__ void xzero_kernel() {
    size_t i = (size_t)blockIdx.x * 1024 + threadIdx.x;
    if (i < X2N / 8) {
        uint4 z = make_uint4(0, 0, 0, 0);
        ((uint4*)X2h)[i] = z;
    }
}

// ---------------- prepass: interior transpose x -> X2h ----------------
__global__ void xprep_kernel(const float* __restrict__ x) {
    extern __shared__ float sp[];
    const int bid = blockIdx.x;
    const int e1  = bid % 24;
    const int cin = (bid / 24) % 32;
    const int b   = bid / 768;
    const int tid = threadIdx.x;

    const float* base = x + (size_t)(b * 32 + cin) * 331776 + e1 * 576;
    for (int i = tid; i < 13824; i += 256) {
        const int e0  = i / 576;
        const int rem = i - e0 * 576;
        sp[e0 * 577 + rem] = __ldg(base + e0 * 13824 + rem);
    }
    __syncthreads();
    const size_t dbase = (size_t)(b * 24 + e1) * 562432 + cin * 26;
    for (int j = tid; j < 13824; j += 256) {
        const int y    = j / 576;
        const int rem2 = j - y * 576;
        const int z    = rem2 / 24;
        const int e0   = rem2 - z * 24;
        X2h[dbase + (size_t)((y + 1) * 26 + (z + 1)) * 832 + (e0 + 1)] =
            __float2half_rn(sp[e0 * 577 + y * 24 + z]);
    }
}

// ---------------- main kernel ----------------
__global__ __launch_bounds__(512, 1)
void conv4d_mma_kernel(const float* __restrict__ bias,
                       float* __restrict__ out)
{
    extern __shared__ float sm[];
    float*    bs  = sm;                       // 64 floats
    uint32_t* A0u = (uint32_t*)(sm + 64);
    uint32_t* A1u = A0u + ASL;
    uint32_t* B0u = A1u + ASL;
    uint32_t* B1u = B0u + BSL;

    const int blk  = blockIdx.x;              // b*576 + d0*24 + d1
    const int d1   = blk % DDIM;
    const int t0   = blk / DDIM;
    const int d0   = t0 % DDIM;
    const int b    = t0 / DDIM;

    const int tid   = threadIdx.x;
    const int wid   = tid >> 5;
    const int lane  = tid & 31;
    const int wm    = wid & 7;                // M slab: anchors [wm*80, +80)
    const int wn    = wid >> 3;               // N half: oc [wn*32, +32)
    const int laneq = lane >> 2;
    const int lanec = lane & 3;

    // ldmatrix per-lane constants
    const int grp      = lane >> 3, lrow = lane & 7;
    const int a_rowoff = ((grp & 1) << 3) + lrow;
    const int a_khalf  = grp >> 1;
    const int b_rowoff = ((grp >> 1) << 3) + lrow;
    const int b_khalf  = grp & 1;
    const uint32_t bxor = (uint32_t)(((b_rowoff >> 1) & 3) << 4);

    if (tid < 64) bs[tid] = bias[tid];

    // zero junk rows (q >= 676) of both A slots, once
    if (tid < 448) {
        A0u[676 * 16 + tid] = 0u;
        A1u[676 * 16 + tid] = 0u;
    }

    // valid (chunk,k1) pairs
    int prs[9]; int np = 0;
    #pragma unroll
    for (int chunk = 0; chunk < 3; chunk++)
        #pragma unroll
        for (int k1 = 0; k1 < 3; k1++) {
            const int e1 = d1 + k1 - 1;
            if ((unsigned)e1 < (unsigned)DDIM) prs[np++] = chunk * 3 + k1;
        }

    float cc[5][4][4];
    #pragma unroll
    for (int i = 0; i < 5; i++)
        #pragma unroll
        for (int j = 0; j < 4; j++)
            #pragma unroll
            for (int k = 0; k < 4; k++) cc[i][j][k] = 0.0f;

    auto stageA = [&](int pr, uint32_t* Ad) {
        const int chunk = pr / 3, k1 = pr - 3 * chunk;
        const int e1 = d1 + k1 - 1;
        const __half* src = X2h + (size_t)(b * 24 + e1) * 562432 + (d0 + chunk) * 32;
        #pragma unroll
        for (int k = 0; k < 11; k++) {
            const int gid = tid + k * 512;
            if (gid < 676 * 8) {
                const int r = gid >> 3, g = gid & 7;
                cpasync8(Ad + r * 16 + (((g >> 1) ^ ((r >> 1) & 3)) << 2) + ((g & 1) << 1),
                         src + (size_t)r * 832 + g * 4);
            }
        }
    };
    auto stageB = [&](int pr, uint32_t* Bd) {
        const __half* wsrc = W2h + pr * 18432;
        #pragma unroll
        for (int i = 0; i < 9; i++) {
            const int gid = tid + i * 512;    // < 4608
            const int tap = gid >> 9, rem = gid & 511;
            const int oc  = rem >> 3, g = rem & 7;
            cpasync8(Bd + tap * 1024 + oc * 16 + (((g >> 1) ^ ((oc >> 1) & 3)) << 2) + ((g & 1) << 1),
                     wsrc + tap * 2048 + oc * 32 + g * 4);
        }
    };

    // prologue: stage iter 0
    stageA(prs[0], A0u);
    stageB(prs[0], B0u);
    asm volatile("cp.async.commit_group;" ::: "memory");
    asm volatile("cp.async.wait_group 0;" ::: "memory");
    __syncthreads();

    const uint32_t aB0 = smem_u32p(A0u), aB1 = smem_u32p(A1u);
    const uint32_t bB0 = smem_u32p(B0u), bB1 = smem_u32p(B1u);
    const uint32_t bRow = (uint32_t)(wn * 32 + b_rowoff) * 64;
    const int arow0 = wm * 80 + a_rowoff;

    for (int it = 0; it < np; it++) {
        const bool more = (it + 1 < np);
        if (more) {                            // hidden behind compute
            stageA(prs[it + 1], (it & 1) ? A0u : A1u);
            stageB(prs[it + 1], (it & 1) ? B0u : B1u);
            asm volatile("cp.async.commit_group;" ::: "memory");
        }

        const uint32_t aB = (it & 1) ? aB1 : aB0;
        const uint32_t bB = ((it & 1) ? bB1 : bB0) + bRow;

        // -------- software-pipelined fragment stream over tk = tap*2+ks --------
        uint32_t ar[2][4], fbr[2][8];
        // preload tk = 0 (tap 0, ks 0, t16 0)
        {
            const int arow = arow0;                      // shift 0
            const uint32_t axor = (uint32_t)(((arow >> 1) & 3) << 4);
            const uint32_t akc  = ((uint32_t)(a_khalf << 4)) ^ axor;
            ldsm4(ar[0], aB + (uint32_t)arow * 64 + akc);
            const uint32_t bkc  = ((uint32_t)(b_khalf << 4)) ^ bxor;
            ldsm4(&fbr[0][0], bB + bkc);
            ldsm4(&fbr[0][4], bB + 1024 + bkc);
        }

        #pragma unroll
        for (int tk = 0; tk < 18; tk++) {
            const int tap = tk >> 1, ks = tk & 1;
            const int shift = (tap / 3) * 26 + (tap % 3);
            const int arow  = arow0 + shift;
            const uint32_t axor  = (uint32_t)(((arow >> 1) & 3) << 4);
            const uint32_t abase = aB + (uint32_t)arow * 64
                                 + (((uint32_t)((ks * 2 + a_khalf) << 4)) ^ axor);
            // next-tk addresses (compile-time after unroll)
            const int tapn = (tk + 1) >> 1, ksn = (tk + 1) & 1;
            const int shiftn = (tapn / 3) * 26 + (tapn % 3);
            const int arown  = arow0 + shiftn;
            const uint32_t axorn  = (uint32_t)(((arown >> 1) & 3) << 4);
            const uint32_t abasen = aB + (uint32_t)arown * 64
                                  + (((uint32_t)((ksn * 2 + a_khalf) << 4)) ^ axorn);
            const uint32_t btapn  = bB + (uint32_t)tapn * 4096;
            const uint32_t bkcn   = ((uint32_t)((ksn * 2 + b_khalf) << 4)) ^ bxor;

            const int fc = tk & 1;            // current fb parity
            #pragma unroll
            for (int t16 = 0; t16 < 5; t16++) {
                const int p  = (tk * 5 + t16) & 1;
                const int pn = p ^ 1;
                // prefetch next a-frag
                if (t16 < 4) {
                    ldsm4(ar[pn], abase + (uint32_t)(t16 + 1) * 1024);
                } else if (tk < 17) {
                    ldsm4(ar[pn], abasen);
                }
                // prefetch next b-frags late in the tile loop
                if (t16 == 3 && tk < 17) {
                    ldsm4(&fbr[fc ^ 1][0], btapn + bkcn);
                    ldsm4(&fbr[fc ^ 1][4], btapn + 1024 + bkcn);
                }
                mma16(cc[t16][0][0], cc[t16][0][1], cc[t16][0][2], cc[t16][0][3],
                      ar[p], fbr[fc][0], fbr[fc][1]);
                mma16(cc[t16][1][0], cc[t16][1][1], cc[t16][1][2], cc[t16][1][3],
                      ar[p], fbr[fc][2], fbr[fc][3]);
                mma16(cc[t16][2][0], cc[t16][2][1], cc[t16][2][2], cc[t16][2][3],
                      ar[p], fbr[fc][4], fbr[fc][5]);
                mma16(cc[t16][3][0], cc[t16][3][1], cc[t16][3][2], cc[t16][3][3],
                      ar[p], fbr[fc][6], fbr[fc][7]);
            }
        }

        if (more) asm volatile("cp.async.wait_group 0;" ::: "memory");
        __syncthreads();
    }

    // epilogue: bias + store valid anchors
    const size_t ob = (size_t)b * 21233664 + (size_t)d0 * 13824 + (size_t)d1 * 576;
    #pragma unroll
    for (int t16 = 0; t16 < 5; t16++) {
        const int qa = wm * 80 + t16 * 16 + laneq;
        const int qb = qa + 8;
        const int p2a = qa / 26, p3a = qa - p2a * 26;
        const int p2b = qb / 26, p3b = qb - p2b * 26;
        const bool va = (p2a < DDIM) && (p3a < DDIM);
        const bool vb = (p2b < DDIM) && (p3b < DDIM);
        #pragma unroll
        for (int n8 = 0; n8 < 4; n8++) {
            const int oc = wn * 32 + n8 * 8 + lanec * 2;
            const float bv0 = bs[oc], bv1 = bs[oc + 1];
            float* o0 = out + ob + (size_t)oc * 331776;
            if (va) {
                o0[p2a * 24 + p3a]          = cc[t16][n8][0] + bv0;
                o0[331776 + p2a * 24 + p3a] = cc[t16][n8][1] + bv1;
            }
            if (vb) {
                o0[p2b * 24 + p3b]          = cc[t16][n8][2] + bv0;
                o0[331776 + p2b * 24 + p3b] = cc[t16][n8][3] + bv1;
            }
        }
    }
}

extern "C" void kernel_launch(void* const* d_in, const int* in_sizes, int n_in,
                              void* d_out, int out_size)
{
    const float* x = nullptr;
    const float* w = nullptr;
    const float* bias = nullptr;
    for (int k = 0; k < n_in; k++) {
        if (in_sizes[k] == 2 * 32 * 24 * 24 * 24 * 24) x    = (const float*)d_in[k];
        else if (in_sizes[k] == 3 * 64 * 32 * 27)      w    = (const float*)d_in[k];
        else if (in_sizes[k] == 64)                    bias = (const float*)d_in[k];
    }
    float* out = (float*)d_out;

    wprep_kernel<<<(165888 + 255) / 256, 256>>>(w);
    xzero_kernel<<<(X2N / 8 + 1023) / 1024, 1024>>>();
    const int xp_smem = 24 * 577 * 4;   // 55392
    cudaFuncSetAttribute(xprep_kernel, cudaFuncAttributeMaxDynamicSharedMemorySize, xp_smem);
    xprep_kernel<<<2 * 32 * 24, 256, xp_smem>>>(x);

    const int smem_bytes = 64 * 4 + (2 * ASL + 2 * BSL) * 4;   // 164096
    cudaFuncSetAttribute(conv4d_mma_kernel, cudaFuncAttributeMaxDynamicSharedMemorySize, smem_bytes);
    conv4d_mma_kernel<<<2 * 24 * 24, 512, smem_bytes>>>(bias, out);
}

// round 17
// speedup vs baseline: 1.3454x; 1.0349x over previous
#include <cuda_runtime.h>
#include <cuda_fp16.h>
#include <cstdint>

// out[b,o,d0,d1,p2,p3] = bias[o] + sum_{chunk,l,k1,k2,k3} w[chunk,o,l,k1,k2,k3] *
//   xp[b, cin, e0, d1+k1-1, p2+k2-1, p3+k3-1],  Labs=(d0+chunk)*32+l, cin=Labs/26, e0=Labs%26-1
// Implicit GEMM via mma.sync m16n8k16 fp16 (fp32 accum), ldmatrix fragments,
// register double-buffered fragments + 16B cp.async staging.
// CTA = (b,d0,d1): D[640 anchors][64 oc], 512 threads (16 warps = 8 M-slabs x 2 N-halves).
// Swizzle (64B rows, 4x16B cols): c16' = c16 ^ ((row>>1)&3).

#define DDIM 24
#define AR 704
#define ASL 11264                // u32 per A slot (AR * 16)
#define BSL 9216                 // u32 per B slot (9 taps * 64 oc * 16)
#define X2N 26996736             // halves: 2*24*676*832

__device__ __align__(16) __half W2h[165888];  // [pr][oc 64][l 32] fp16
__device__ __align__(16) __half X2h[X2N];     // [b][e1][q 676][Labs 832] fp16, borders zero

__device__ __forceinline__ uint32_t smem_u32p(const void* p) {
    return (uint32_t)__cvta_generic_to_shared(p);
}
__device__ __forceinline__ void cpasync16(const uint32_t* smem_dst, const __half* gsrc) {
    unsigned a = (unsigned)__cvta_generic_to_shared(smem_dst);
    asm volatile("cp.async.cg.shared.global [%0], [%1], 16;" :: "r"(a), "l"(gsrc) : "memory");
}
__device__ __forceinline__ void ldsm4(uint32_t* r, uint32_t addr) {
    asm volatile("ldmatrix.sync.aligned.m8n8.x4.shared.b16 {%0,%1,%2,%3}, [%4];"
                 : "=r"(r[0]), "=r"(r[1]), "=r"(r[2]), "=r"(r[3]) : "r"(addr));
}
__device__ __forceinline__ void mma16(float& c0, float& c1, float& c2, float& c3,
                                      const uint32_t* a, uint32_t b0, uint32_t b1) {
    asm volatile("mma.sync.aligned.m16n8k16.row.col.f32.f16.f16.f32 "
                 "{%0,%1,%2,%3},{%4,%5,%6,%7},{%8,%9},{%0,%1,%2,%3};"
                 : "+f"(c0), "+f"(c1), "+f"(c2), "+f"(c3)
                 : "r"(a[0]), "r"(a[1]), "r"(a[2]), "r"(a[3]), "r"(b0), "r"(b1));
}

// ---------------- prepass: weights ----------------
__global__ void wprep_kernel(const float* __restrict__ w) {
    int idx = blockIdx.x * 256 + threadIdx.x;
    if (idx < 165888) {
        int l = idx & 31;
        int r = idx >> 5;
        int oc = r & 63; r >>= 6;
        int t = r % 9;  r /= 9;
        int k1 = r % 3;
        int chunk = r / 3;
        W2h[idx] = __float2half_rn(w[((chunk * 64 + oc) * 32 + l) * 27 + k1 * 9 + t]);
    }
}

// ---------------- prepass: zero X2h ----------------
__global__ void xzero_kernel() {
    size_t i = (size_t)blockIdx.x * 1024 + threadIdx.x;
    if (i < X2N / 8) {
        uint4 z = make_uint4(0, 0, 0, 0);
        ((uint4*)X2h)[i] = z;
    }
}

// ---------------- prepass: interior transpose x -> X2h ----------------
__global__ void xprep_kernel(const float* __restrict__ x) {
    extern __shared__ float sp[];
    const int bid = blockIdx.x;
    const int e1  = bid % 24;
    const int cin = (bid / 24) % 32;
    const int b   = bid / 768;
    const int tid = threadIdx.x;

    const float* base = x + (size_t)(b * 32 + cin) * 331776 + e1 * 576;
    for (int i = tid; i < 13824; i += 256) {
        const int e0  = i / 576;
        const int rem = i - e0 * 576;
        sp[e0 * 577 + rem] = __ldg(base + e0 * 13824 + rem);
    }
    __syncthreads();
    const size_t dbase = (size_t)(b * 24 + e1) * 562432 + cin * 26;
    for (int j = tid; j < 13824; j += 256) {
        const int y    = j / 576;
        const int rem2 = j - y * 576;
        const int z    = rem2 / 24;
        const int e0   = rem2 - z * 24;
        X2h[dbase + (size_t)((y + 1) * 26 + (z + 1)) * 832 + (e0 + 1)] =
            __float2half_rn(sp[e0 * 577 + y * 24 + z]);
    }
}

// ---------------- main kernel ----------------
__global__ __launch_bounds__(512, 1)
void conv4d_mma_kernel(const float* __restrict__ bias,
                       float* __restrict__ out)
{
    extern __shared__ float sm[];
    float*    bs  = sm;                       // 64 floats
    uint32_t* A0u = (uint32_t*)(sm + 64);
    uint32_t* A1u = A0u + ASL;
    uint32_t* B0u = A1u + ASL;
    uint32_t* B1u = B0u + BSL;

    const int blk  = blockIdx.x;              // b*576 + d0*24 + d1
    const int d1   = blk % DDIM;
    const int t0   = blk / DDIM;
    const int d0   = t0 % DDIM;
    const int b    = t0 / DDIM;

    const int tid   = threadIdx.x;
    const int wid   = tid >> 5;
    const int lane  = tid & 31;
    const int wm    = wid & 7;                // M slab: anchors [wm*80, +80)
    const int wn    = wid >> 3;               // N half: oc [wn*32, +32)
    const int laneq = lane >> 2;
    const int lanec = lane & 3;

    // ldmatrix per-lane constants
    const int grp      = lane >> 3, lrow = lane & 7;
    const int a_rowoff = ((grp & 1) << 3) + lrow;
    const int a_khalf  = grp >> 1;
    const int b_rowoff = ((grp >> 1) << 3) + lrow;
    const int b_khalf  = grp & 1;
    const uint32_t bxor = (uint32_t)(((b_rowoff >> 1) & 3) << 4);

    if (tid < 64) bs[tid] = bias[tid];

    // zero junk rows (q >= 676) of both A slots, once
    if (tid < 448) {
        A0u[676 * 16 + tid] = 0u;
        A1u[676 * 16 + tid] = 0u;
    }

    // valid (chunk,k1) pairs
    int prs[9]; int np = 0;
    #pragma unroll
    for (int chunk = 0; chunk < 3; chunk++)
        #pragma unroll
        for (int k1 = 0; k1 < 3; k1++) {
            const int e1 = d1 + k1 - 1;
            if ((unsigned)e1 < (unsigned)DDIM) prs[np++] = chunk * 3 + k1;
        }

    float cc[5][4][4];
    #pragma unroll
    for (int i = 0; i < 5; i++)
        #pragma unroll
        for (int j = 0; j < 4; j++)
            #pragma unroll
            for (int k = 0; k < 4; k++) cc[i][j][k] = 0.0f;

    // 16B-granule staging: granule g16 of row r -> u32 idx = r*16 + (g16 ^ ((r>>1)&3))*4
    auto stageA = [&](int pr, uint32_t* Ad) {
        const int chunk = pr / 3, k1 = pr - 3 * chunk;
        const int e1 = d1 + k1 - 1;
        const __half* src = X2h + (size_t)(b * 24 + e1) * 562432 + (d0 + chunk) * 32;
        #pragma unroll
        for (int k = 0; k < 6; k++) {
            const int gid = tid + k * 512;
            if (gid < 676 * 4) {
                const int r = gid >> 2, g = gid & 3;
                cpasync16(Ad + r * 16 + ((g ^ ((r >> 1) & 3)) << 2),
                          src + (size_t)r * 832 + g * 8);
            }
        }
    };
    auto stageB = [&](int pr, uint32_t* Bd) {
        const __half* wsrc = W2h + pr * 18432;
        #pragma unroll
        for (int i = 0; i < 5; i++) {
            const int gid = tid + i * 512;    // < 2304
            if (gid < 2304) {
                const int tap = gid >> 8, rem = gid & 255;
                const int oc  = rem >> 2, g = rem & 3;
                cpasync16(Bd + tap * 1024 + oc * 16 + ((g ^ ((oc >> 1) & 3)) << 2),
                          wsrc + tap * 2048 + oc * 32 + g * 8);
            }
        }
    };

    // prologue: stage iter 0
    stageA(prs[0], A0u);
    stageB(prs[0], B0u);
    asm volatile("cp.async.commit_group;" ::: "memory");
    asm volatile("cp.async.wait_group 0;" ::: "memory");
    __syncthreads();

    const uint32_t aB0 = smem_u32p(A0u), aB1 = smem_u32p(A1u);
    const uint32_t bB0 = smem_u32p(B0u), bB1 = smem_u32p(B1u);
    const uint32_t bRow = (uint32_t)(wn * 32 + b_rowoff) * 64;
    const int arow0 = wm * 80 + a_rowoff;

    for (int it = 0; it < np; it++) {
        const bool more = (it + 1 < np);

        const uint32_t aB = (it & 1) ? aB1 : aB0;
        const uint32_t bB = ((it & 1) ? bB1 : bB0) + bRow;

        // -------- preload tk=0 fragments BEFORE issuing next-iter staging --------
        uint32_t ar[2][4], fbr[2][8];
        {
            const int arow = arow0;                      // shift 0
            const uint32_t axor = (uint32_t)(((arow >> 1) & 3) << 4);
            const uint32_t akc  = ((uint32_t)(a_khalf << 4)) ^ axor;
            ldsm4(ar[0], aB + (uint32_t)arow * 64 + akc);
            const uint32_t bkc  = ((uint32_t)(b_khalf << 4)) ^ bxor;
            ldsm4(&fbr[0][0], bB + bkc);
            ldsm4(&fbr[0][4], bB + 1024 + bkc);
        }

        if (more) {                            // hidden behind compute
            stageA(prs[it + 1], (it & 1) ? A0u : A1u);
            stageB(prs[it + 1], (it & 1) ? B0u : B1u);
            asm volatile("cp.async.commit_group;" ::: "memory");
        }

        #pragma unroll
        for (int tk = 0; tk < 18; tk++) {
            const int tap = tk >> 1, ks = tk & 1;
            const int shift = (tap / 3) * 26 + (tap % 3);
            const int arow  = arow0 + shift;
            const uint32_t axor  = (uint32_t)(((arow >> 1) & 3) << 4);
            const uint32_t abase = aB + (uint32_t)arow * 64
                                 + (((uint32_t)((ks * 2 + a_khalf) << 4)) ^ axor);
            const int tapn = (tk + 1) >> 1, ksn = (tk + 1) & 1;
            const int shiftn = (tapn / 3) * 26 + (tapn % 3);
            const int arown  = arow0 + shiftn;
            const uint32_t axorn  = (uint32_t)(((arown >> 1) & 3) << 4);
            const uint32_t abasen = aB + (uint32_t)arown * 64
                                  + (((uint32_t)((ksn * 2 + a_khalf) << 4)) ^ axorn);
            const uint32_t btapn  = bB + (uint32_t)tapn * 4096;
            const uint32_t bkcn   = ((uint32_t)((ksn * 2 + b_khalf) << 4)) ^ bxor;

            const int fc = tk & 1;
            #pragma unroll
            for (int t16 = 0; t16 < 5; t16++) {
                const int p  = (tk * 5 + t16) & 1;
                const int pn = p ^ 1;
                if (t16 < 4) {
                    ldsm4(ar[pn], abase + (uint32_t)(t16 + 1) * 1024);
                } else if (tk < 17) {
                    ldsm4(ar[pn], abasen);
                }
                if (t16 == 3 && tk < 17) {
                    ldsm4(&fbr[fc ^ 1][0], btapn + bkcn);
                    ldsm4(&fbr[fc ^ 1][4], btapn + 1024 + bkcn);
                }
                mma16(cc[t16][0][0], cc[t16][0][1], cc[t16][0][2], cc[t16][0][3],
                      ar[p], fbr[fc][0], fbr[fc][1]);
                mma16(cc[t16][1][0], cc[t16][1][1], cc[t16][1][2], cc[t16][1][3],
                      ar[p], fbr[fc][2], fbr[fc][3]);
                mma16(cc[t16][2][0], cc[t16][2][1], cc[t16][2][2], cc[t16][2][3],
                      ar[p], fbr[fc][4], fbr[fc][5]);
                mma16(cc[t16][3][0], cc[t16][3][1], cc[t16][3][2], cc[t16][3][3],
                      ar[p], fbr[fc][6], fbr[fc][7]);
            }
        }

        if (more) asm volatile("cp.async.wait_group 0;" ::: "memory");
        __syncthreads();
    }

    // epilogue: bias + store valid anchors
    const size_t ob = (size_t)b * 21233664 + (size_t)d0 * 13824 + (size_t)d1 * 576;
    #pragma unroll
    for (int t16 = 0; t16 < 5; t16++) {
        const int qa = wm * 80 + t16 * 16 + laneq;
        const int qb = qa + 8;
        const int p2a = qa / 26, p3a = qa - p2a * 26;
        const int p2b = qb / 26, p3b = qb - p2b * 26;
        const bool va = (p2a < DDIM) && (p3a < DDIM);
        const bool vb = (p2b < DDIM) && (p3b < DDIM);
        #pragma unroll
        for (int n8 = 0; n8 < 4; n8++) {
            const int oc = wn * 32 + n8 * 8 + lanec * 2;
            const float bv0 = bs[oc], bv1 = bs[oc + 1];
            float* o0 = out + ob + (size_t)oc * 331776;
            if (va) {
                o0[p2a * 24 + p3a]          = cc[t16][n8][0] + bv0;
                o0[331776 + p2a * 24 + p3a] = cc[t16][n8][1] + bv1;
            }
            if (vb) {
                o0[p2b * 24 + p3b]          = cc[t16][n8][2] + bv0;
                o0[331776 + p2b * 24 + p3b] = cc[t16][n8][3] + bv1;
            }
        }
    }
}

extern "C" void kernel_launch(void* const* d_in, const int* in_sizes, int n_in,
                              void* d_out, int out_size)
{
    const float* x = nullptr;
    const float* w = nullptr;
    const float* bias = nullptr;
    for (int k = 0; k < n_in; k++) {
        if (in_sizes[k] == 2 * 32 * 24 * 24 * 24 * 24) x    = (const float*)d_in[k];
        else if (in_sizes[k] == 3 * 64 * 32 * 27)      w    = (const float*)d_in[k];
        else if (in_sizes[k] == 64)                    bias = (const float*)d_in[k];
    }
    float* out = (float*)d_out;

    wprep_kernel<<<(165888 + 255) / 256, 256>>>(w);
    xzero_kernel<<<(X2N / 8 + 1023) / 1024, 1024>>>();
    const int xp_smem = 24 * 577 * 4;   // 55392
    cudaFuncSetAttribute(xprep_kernel, cudaFuncAttributeMaxDynamicSharedMemorySize, xp_smem);
    xprep_kernel<<<2 * 32 * 24, 256, xp_smem>>>(x);

    const int smem_bytes = 64 * 4 + (2 * ASL + 2 * BSL) * 4;   // 164096
    cudaFuncSetAttribute(conv4d_mma_kernel, cudaFuncAttributeMaxDynamicSharedMemorySize, smem_bytes);
    conv4d_mma_kernel<<<2 * 24 * 24, 512, smem_bytes>>>(bias, out);
}